// round 1
// baseline (speedup 1.0000x reference)
#include <cuda_runtime.h>
#include <math.h>
#include <float.h>

#define NN 50000
#define EE 150000
#define DD 128
#define HH 4
#define EDIM 16
#define ZCOLS 2304
// Z column layout: [xWr | xWskip+b | Q | K | V | G]
#define ZOFF_R 0
#define ZOFF_SKIP 128
#define ZOFF_Q 256
#define ZOFF_K 768
#define ZOFF_V 1280
#define ZOFF_G 1792

// ---------------- scratch (static device allocations; no cudaMalloc) ----------
__device__ float g_Z[(size_t)NN * ZCOLS];      // 460.8 MB packed node GEMM output
__device__ float g_Wpack[DD * ZCOLS];
__device__ float g_bpack[ZCOLS];
__device__ float g_agg[NN * DD];               // SAGE sum -> mean (in place)
__device__ float g_cnt[NN];
__device__ float g_mw[NN * DD];                // mean @ sage_Wl
__device__ float g_mt[NN * HH];                // transformer seg-max
__device__ float g_st[NN * HH];                // transformer seg-sum
__device__ float g_elog[EE * HH];              // transformer logits -> exp values
__device__ float g_outt[NN * DD];              // transformer aggregation
__device__ float g_as[NN * HH];
__device__ float g_ad[NN * HH];
__device__ float g_gm[NN * HH];                // GAT seg-max
__device__ float g_gsum[NN * HH];              // GAT seg-sum
__device__ float g_glog[EE * HH];              // GAT edge logits -> exp
__device__ float g_lself[NN * HH];             // GAT self-loop logits -> exp
__device__ float g_outg[NN * DD];              // GAT aggregation
__device__ float g_cat[NN * 3 * DD];
__device__ float g_y[NN * DD];                 // cat @ fus_W + fus_b

// ---------------- helpers ------------------------------------------------------
__device__ __forceinline__ void atomicMaxFloat(float* addr, float val) {
    int* a = (int*)addr;
    int old = __float_as_int(*addr);
    while (__int_as_float(old) < val) {
        int prev = atomicCAS(a, old, __float_as_int(val));
        if (prev == old) break;
        old = prev;
    }
}

// ---------------- init ---------------------------------------------------------
__global__ void k_init() {
    int i = blockIdx.x * blockDim.x + threadIdx.x;
    if (i < NN * DD) {
        g_agg[i] = 0.f; g_outt[i] = 0.f; g_outg[i] = 0.f;
    }
    if (i < NN) g_cnt[i] = 0.f;
    if (i < NN * HH) {
        g_mt[i] = -FLT_MAX; g_st[i] = 0.f;
        g_gm[i] = -FLT_MAX; g_gsum[i] = 0.f;
    }
}

// ---------------- pack weights [sage_Wr | tskip | Q | K | V | G] ---------------
__global__ void k_pack(const float* __restrict__ Wr, const float* __restrict__ Wsk,
                       const float* __restrict__ Wq, const float* __restrict__ Wk,
                       const float* __restrict__ Wv, const float* __restrict__ Wg,
                       const float* __restrict__ sb, const float* __restrict__ skb,
                       const float* __restrict__ qb, const float* __restrict__ kb,
                       const float* __restrict__ vb) {
    int i = blockIdx.x * blockDim.x + threadIdx.x;
    if (i >= DD * ZCOLS) return;
    int k = i / ZCOLS, c = i % ZCOLS;
    float w;
    if (c < 256) {
        w = (c < 128) ? Wr[k * 128 + c] : Wsk[k * 128 + (c - 128)];
    } else if (c < 768)      w = Wq[k * 512 + (c - ZOFF_Q)];
    else if (c < 1280)       w = Wk[k * 512 + (c - ZOFF_K)];
    else if (c < 1792)       w = Wv[k * 512 + (c - ZOFF_V)];
    else                     w = Wg[k * 512 + (c - ZOFF_G)];
    g_Wpack[i] = w;
    if (k == 0) {
        float b;
        if (c < 128)        b = sb[c];
        else if (c < 256)   b = skb[c - 128];
        else if (c < 768)   b = qb[c - ZOFF_Q];
        else if (c < 1280)  b = kb[c - ZOFF_K];
        else if (c < 1792)  b = vb[c - ZOFF_V];
        else                b = 0.f;
        g_bpack[c] = b;
    }
}

// ---------------- SAGE neighbor scatter ----------------------------------------
__global__ void k_sage_scatter(const float* __restrict__ x, const int* __restrict__ ei) {
    int e = blockIdx.x, t = threadIdx.x;
    int src = ei[e], dst = ei[EE + e];
    atomicAdd(&g_agg[dst * DD + t], x[src * DD + t]);
    if (t == 0) atomicAdd(&g_cnt[dst], 1.f);
}

__global__ void k_mean() {
    int i = blockIdx.x * blockDim.x + threadIdx.x;
    if (i >= NN * DD) return;
    float c = g_cnt[i / DD];
    g_agg[i] = g_agg[i] / fmaxf(c, 1.f);
}

// ---------------- generic SGEMM: C[M,N] = A[M,K]*B[K,N] (+bias) ----------------
// BM=BN=128, BK=8, 256 threads, 8x8 per thread, float4 loads.
__global__ void sgemm128(const float* __restrict__ A, const float* __restrict__ B,
                         const float* __restrict__ bias, float* __restrict__ C,
                         int M, int N, int K) {
    __shared__ float As[8][128];
    __shared__ float Bs[8][128];
    int tid = threadIdx.x;
    int tx = tid & 15, ty = tid >> 4;
    int rowBase = blockIdx.y * 128, colBase = blockIdx.x * 128;
    float acc[8][8];
#pragma unroll
    for (int i = 0; i < 8; i++)
#pragma unroll
        for (int j = 0; j < 8; j++) acc[i][j] = 0.f;
    int ar = tid >> 1, ac = (tid & 1) * 4;      // A: 128 rows x 8 cols
    int br = tid >> 5, bc = (tid & 31) * 4;     // B: 8 rows x 128 cols

    for (int k0 = 0; k0 < K; k0 += 8) {
        float4 av;
        int gr = rowBase + ar;
        if (gr < M) av = *reinterpret_cast<const float4*>(&A[(size_t)gr * K + k0 + ac]);
        else av = make_float4(0.f, 0.f, 0.f, 0.f);
        float4 bv = *reinterpret_cast<const float4*>(&B[(size_t)(k0 + br) * N + colBase + bc]);
        __syncthreads();
        As[ac + 0][ar] = av.x; As[ac + 1][ar] = av.y;
        As[ac + 2][ar] = av.z; As[ac + 3][ar] = av.w;
        *reinterpret_cast<float4*>(&Bs[br][bc]) = bv;
        __syncthreads();
#pragma unroll
        for (int kk = 0; kk < 8; kk++) {
            float a0[8], b0[8];
            float4 a01 = *reinterpret_cast<const float4*>(&As[kk][ty * 8]);
            float4 a23 = *reinterpret_cast<const float4*>(&As[kk][ty * 8 + 4]);
            float4 b01 = *reinterpret_cast<const float4*>(&Bs[kk][tx * 8]);
            float4 b23 = *reinterpret_cast<const float4*>(&Bs[kk][tx * 8 + 4]);
            a0[0]=a01.x;a0[1]=a01.y;a0[2]=a01.z;a0[3]=a01.w;
            a0[4]=a23.x;a0[5]=a23.y;a0[6]=a23.z;a0[7]=a23.w;
            b0[0]=b01.x;b0[1]=b01.y;b0[2]=b01.z;b0[3]=b01.w;
            b0[4]=b23.x;b0[5]=b23.y;b0[6]=b23.z;b0[7]=b23.w;
#pragma unroll
            for (int i = 0; i < 8; i++)
#pragma unroll
                for (int j = 0; j < 8; j++) acc[i][j] += a0[i] * b0[j];
        }
    }
#pragma unroll
    for (int i = 0; i < 8; i++) {
        int gr = rowBase + ty * 8 + i;
        if (gr >= M) continue;
        int gc = colBase + tx * 8;
        float4 o0, o1;
        float b0 = bias ? bias[gc + 0] : 0.f, b1 = bias ? bias[gc + 1] : 0.f;
        float b2 = bias ? bias[gc + 2] : 0.f, b3 = bias ? bias[gc + 3] : 0.f;
        float b4 = bias ? bias[gc + 4] : 0.f, b5 = bias ? bias[gc + 5] : 0.f;
        float b6 = bias ? bias[gc + 6] : 0.f, b7 = bias ? bias[gc + 7] : 0.f;
        o0 = make_float4(acc[i][0] + b0, acc[i][1] + b1, acc[i][2] + b2, acc[i][3] + b3);
        o1 = make_float4(acc[i][4] + b4, acc[i][5] + b5, acc[i][6] + b6, acc[i][7] + b7);
        *reinterpret_cast<float4*>(&C[(size_t)gr * N + gc]) = o0;
        *reinterpret_cast<float4*>(&C[(size_t)gr * N + gc + 4]) = o1;
    }
}

// ---------------- GAT attention coefficients a_s, a_d --------------------------
__global__ void k_asad(const float* __restrict__ attS, const float* __restrict__ attD) {
    int w = (blockIdx.x * blockDim.x + threadIdx.x) >> 5;
    int lane = threadIdx.x & 31;
    if (w >= NN * HH) return;
    int n = w / HH, h = w % HH;
    const float* g = g_Z + (size_t)n * ZCOLS + ZOFF_G + h * DD;
    float s = 0.f, d = 0.f;
    for (int i = lane; i < DD; i += 32) {
        float gv = g[i];
        s += gv * attS[h * DD + i];
        d += gv * attD[h * DD + i];
    }
#pragma unroll
    for (int o = 16; o; o >>= 1) {
        s += __shfl_xor_sync(0xffffffffu, s, o);
        d += __shfl_xor_sync(0xffffffffu, d, o);
    }
    if (lane == 0) { g_as[n * HH + h] = s; g_ad[n * HH + h] = d; }
}

// ---------------- transformer edge logits + seg-max ----------------------------
__global__ void k_tlogit(const int* __restrict__ ei, const float* __restrict__ ea,
                         const float* __restrict__ teW) {
    int e = blockIdx.x, t = threadIdx.x;
    int src = ei[e], dst = ei[EE + e];
    __shared__ float sea[EDIM];
    __shared__ float red[HH][4];
    if (t < EDIM) sea[t] = ea[e * EDIM + t];
    __syncthreads();
    float acc[HH];
#pragma unroll
    for (int h = 0; h < HH; h++) {
        float ev = 0.f;
#pragma unroll
        for (int j = 0; j < EDIM; j++) ev += sea[j] * teW[j * 512 + h * DD + t];
        float qv = g_Z[(size_t)dst * ZCOLS + ZOFF_Q + h * DD + t];
        float kv = g_Z[(size_t)src * ZCOLS + ZOFF_K + h * DD + t];
        acc[h] = qv * (kv + ev);
    }
    int lane = t & 31, wp = t >> 5;
#pragma unroll
    for (int h = 0; h < HH; h++) {
        float v = acc[h];
#pragma unroll
        for (int o = 16; o; o >>= 1) v += __shfl_xor_sync(0xffffffffu, v, o);
        if (lane == 0) red[h][wp] = v;
    }
    __syncthreads();
    if (t < HH) {
        float v = (red[t][0] + red[t][1] + red[t][2] + red[t][3]) * 0.0883883476483184405f;
        g_elog[e * HH + t] = v;
        atomicMaxFloat(&g_mt[dst * HH + t], v);
    }
}

__global__ void k_texp(const int* __restrict__ ei) {
    int i = blockIdx.x * blockDim.x + threadIdx.x;
    if (i >= EE * HH) return;
    int e = i / HH, h = i % HH;
    int dst = ei[EE + e];
    float v = expf(g_elog[i] - g_mt[dst * HH + h]);
    g_elog[i] = v;
    atomicAdd(&g_st[dst * HH + h], v);
}

__global__ void k_taggr(const int* __restrict__ ei, const float* __restrict__ ea,
                        const float* __restrict__ teW) {
    int e = blockIdx.x, t = threadIdx.x;
    int src = ei[e], dst = ei[EE + e];
    __shared__ float sea[EDIM];
    __shared__ float w[HH];
    if (t < EDIM) sea[t] = ea[e * EDIM + t];
    if (t < HH) w[t] = g_elog[e * HH + t] / (g_st[dst * HH + t] + 1e-16f) * 0.25f;
    __syncthreads();
    float acc = 0.f;
#pragma unroll
    for (int h = 0; h < HH; h++) {
        float ev = 0.f;
#pragma unroll
        for (int j = 0; j < EDIM; j++) ev += sea[j] * teW[j * 512 + h * DD + t];
        float vv = g_Z[(size_t)src * ZCOLS + ZOFF_V + h * DD + t];
        acc += w[h] * (vv + ev);
    }
    atomicAdd(&g_outt[dst * DD + t], acc);
}

// ---------------- GAT logits / softmax / aggregation (edges + self loops) ------
__global__ void k_glogit(const int* __restrict__ ei) {
    int i = blockIdx.x * blockDim.x + threadIdx.x;
    if (i < EE * HH) {
        int e = i / HH, h = i % HH;
        int s = ei[e], d = ei[EE + e];
        float v = g_as[s * HH + h] + g_ad[d * HH + h];
        v = (v > 0.f) ? v : 0.2f * v;
        g_glog[i] = v;
        atomicMaxFloat(&g_gm[d * HH + h], v);
    } else if (i < (EE + NN) * HH) {
        int j = i - EE * HH;
        int n = j / HH, h = j % HH;
        float v = g_as[n * HH + h] + g_ad[n * HH + h];
        v = (v > 0.f) ? v : 0.2f * v;
        g_lself[j] = v;
        atomicMaxFloat(&g_gm[n * HH + h], v);
    }
}

__global__ void k_gexp(const int* __restrict__ ei) {
    int i = blockIdx.x * blockDim.x + threadIdx.x;
    if (i < EE * HH) {
        int e = i / HH, h = i % HH;
        int d = ei[EE + e];
        float v = expf(g_glog[i] - g_gm[d * HH + h]);
        g_glog[i] = v;
        atomicAdd(&g_gsum[d * HH + h], v);
    } else if (i < (EE + NN) * HH) {
        int j = i - EE * HH;
        int n = j / HH, h = j % HH;
        float v = expf(g_lself[j] - g_gm[n * HH + h]);
        g_lself[j] = v;
        atomicAdd(&g_gsum[n * HH + h], v);
    }
}

__global__ void k_gaggr(const int* __restrict__ ei) {
    int b = blockIdx.x, t = threadIdx.x;
    int src, dst;
    const float* lw;
    if (b < EE) { src = ei[b]; dst = ei[EE + b]; lw = &g_glog[b * HH]; }
    else        { src = b - EE; dst = src;       lw = &g_lself[src * HH]; }
    __shared__ float w[HH];
    if (t < HH) w[t] = lw[t] / (g_gsum[dst * HH + t] + 1e-16f) * 0.25f;
    __syncthreads();
    float acc = 0.f;
#pragma unroll
    for (int h = 0; h < HH; h++)
        acc += w[h] * g_Z[(size_t)src * ZCOLS + ZOFF_G + h * DD + t];
    atomicAdd(&g_outg[dst * DD + t], acc);
}

// ---------------- combine branches into cat ------------------------------------
__global__ void k_combine(const float* __restrict__ gatb,
                          const float* __restrict__ gsh, const float* __restrict__ gatt,
                          const float* __restrict__ gnb) {
    int i = blockIdx.x * blockDim.x + threadIdx.x;
    if (i >= NN * DD) return;
    int n = i / DD, d = i % DD;
    float s_s = 1.f / (1.f + expf(-gsh[0]));
    float s_a = 1.f / (1.f + expf(-gatt[0]));
    float s_n = 1.f / (1.f + expf(-gnb[0]));
    float xs = g_mw[i] + g_Z[(size_t)n * ZCOLS + ZOFF_R + d];       // sage_b already in bpack
    xs = fmaxf(xs, 0.f);
    float xa = g_outt[i] + g_Z[(size_t)n * ZCOLS + ZOFF_SKIP + d];  // tskip_b in bpack
    xa = fmaxf(xa, 0.f);
    float xn = fmaxf(g_outg[i] + gatb[d], 0.f);
    g_cat[(size_t)n * 384 + d]       = xs * s_s;
    g_cat[(size_t)n * 384 + 128 + d] = xa * s_a;
    g_cat[(size_t)n * 384 + 256 + d] = xn * s_n;
}

// ---------------- final: LN -> relu -> residual -> LN ---------------------------
__global__ void k_final(const float* __restrict__ x,
                        const float* __restrict__ fg, const float* __restrict__ fb,
                        const float* __restrict__ ng, const float* __restrict__ nb,
                        float* __restrict__ out) {
    int n = blockIdx.x, t = threadIdx.x;
    __shared__ float sh[4];
    float v = g_y[n * DD + t];
    float s = v;
#pragma unroll
    for (int o = 16; o; o >>= 1) s += __shfl_xor_sync(0xffffffffu, s, o);
    if ((t & 31) == 0) sh[t >> 5] = s;
    __syncthreads();
    float mean = (sh[0] + sh[1] + sh[2] + sh[3]) * (1.f / DD);
    __syncthreads();
    float dv = v - mean;
    float s2 = dv * dv;
#pragma unroll
    for (int o = 16; o; o >>= 1) s2 += __shfl_xor_sync(0xffffffffu, s2, o);
    if ((t & 31) == 0) sh[t >> 5] = s2;
    __syncthreads();
    float var = (sh[0] + sh[1] + sh[2] + sh[3]) * (1.f / DD);
    float ln1 = dv * rsqrtf(var + 1e-5f) * fg[t] + fb[t];
    float r = x[n * DD + t] + fmaxf(ln1, 0.f);
    __syncthreads();
    s = r;
#pragma unroll
    for (int o = 16; o; o >>= 1) s += __shfl_xor_sync(0xffffffffu, s, o);
    if ((t & 31) == 0) sh[t >> 5] = s;
    __syncthreads();
    float mean2 = (sh[0] + sh[1] + sh[2] + sh[3]) * (1.f / DD);
    __syncthreads();
    float dr = r - mean2;
    s2 = dr * dr;
#pragma unroll
    for (int o = 16; o; o >>= 1) s2 += __shfl_xor_sync(0xffffffffu, s2, o);
    if ((t & 31) == 0) sh[t >> 5] = s2;
    __syncthreads();
    float var2 = (sh[0] + sh[1] + sh[2] + sh[3]) * (1.f / DD);
    out[n * DD + t] = dr * rsqrtf(var2 + 1e-5f) * ng[t] + nb[t];
}

// ---------------- launch --------------------------------------------------------
extern "C" void kernel_launch(void* const* d_in, const int* in_sizes, int n_in,
                              void* d_out, int out_size) {
    const float* x       = (const float*)d_in[0];
    const int*   ei      = (const int*)d_in[1];
    const float* ea      = (const float*)d_in[2];
    const float* sage_Wl = (const float*)d_in[3];
    const float* sage_Wr = (const float*)d_in[4];
    const float* sage_b  = (const float*)d_in[5];
    const float* tqW = (const float*)d_in[6];
    const float* tqb = (const float*)d_in[7];
    const float* tkW = (const float*)d_in[8];
    const float* tkb = (const float*)d_in[9];
    const float* tvW = (const float*)d_in[10];
    const float* tvb = (const float*)d_in[11];
    const float* teW = (const float*)d_in[12];
    const float* tskW = (const float*)d_in[13];
    const float* tskb = (const float*)d_in[14];
    const float* gatW = (const float*)d_in[15];
    const float* attS = (const float*)d_in[16];
    const float* attD = (const float*)d_in[17];
    const float* gatb = (const float*)d_in[18];
    const float* gsh  = (const float*)d_in[19];
    const float* gatt = (const float*)d_in[20];
    const float* gnb  = (const float*)d_in[21];
    const float* fusW = (const float*)d_in[22];
    const float* fusb = (const float*)d_in[23];
    const float* fusg = (const float*)d_in[24];
    const float* fusbe = (const float*)d_in[25];
    const float* ng   = (const float*)d_in[26];
    const float* nb   = (const float*)d_in[27];
    float* out = (float*)d_out;

    float *pZ, *pWp, *pbp, *pagg, *pmw, *pcat, *py;
    cudaGetSymbolAddress((void**)&pZ, g_Z);
    cudaGetSymbolAddress((void**)&pWp, g_Wpack);
    cudaGetSymbolAddress((void**)&pbp, g_bpack);
    cudaGetSymbolAddress((void**)&pagg, g_agg);
    cudaGetSymbolAddress((void**)&pmw, g_mw);
    cudaGetSymbolAddress((void**)&pcat, g_cat);
    cudaGetSymbolAddress((void**)&py, g_y);

    k_init<<<(NN * DD + 255) / 256, 256>>>();
    k_pack<<<(DD * ZCOLS + 255) / 256, 256>>>(sage_Wr, tskW, tqW, tkW, tvW, gatW,
                                              sage_b, tskb, tqb, tkb, tvb);
    k_sage_scatter<<<EE, DD>>>(x, ei);

    dim3 gZ(ZCOLS / 128, (NN + 127) / 128);
    sgemm128<<<gZ, 256>>>(x, pWp, pbp, pZ, NN, ZCOLS, DD);

    k_mean<<<(NN * DD + 255) / 256, 256>>>();
    sgemm128<<<dim3(1, (NN + 127) / 128), 256>>>(pagg, sage_Wl, nullptr, pmw, NN, DD, DD);

    k_asad<<<(NN * HH * 32 + 255) / 256, 256>>>(attS, attD);

    k_tlogit<<<EE, DD>>>(ei, ea, teW);
    k_texp<<<(EE * HH + 255) / 256, 256>>>(ei);
    k_taggr<<<EE, DD>>>(ei, ea, teW);

    k_glogit<<<((EE + NN) * HH + 255) / 256, 256>>>(ei);
    k_gexp<<<((EE + NN) * HH + 255) / 256, 256>>>(ei);
    k_gaggr<<<EE + NN, DD>>>(ei);

    k_combine<<<(NN * DD + 255) / 256, 256>>>(gatb, gsh, gatt, gnb);
    sgemm128<<<dim3(1, (NN + 127) / 128), 256>>>(pcat, fusW, fusb, py, NN, DD, 3 * DD);
    k_final<<<NN, DD>>>(x, fusg, fusbe, ng, nb, out);
}

// round 2
// speedup vs baseline: 1.3517x; 1.3517x over previous
#include <cuda_runtime.h>
#include <math.h>
#include <float.h>

#define NN 50000
#define EE 150000
#define DD 128
#define HH 4
#define EDIM 16
#define ZCOLS 2304
// Z column layout: [xWr | xWskip+b | Q | K | V | G]
#define ZOFF_R 0
#define ZOFF_SKIP 128
#define ZOFF_Q 256
#define ZOFF_K 768
#define ZOFF_V 1280
#define ZOFF_G 1792

// ---------------- scratch (static device allocations; no cudaMalloc) ----------
__device__ float g_Z[(size_t)NN * ZCOLS];      // 460.8 MB packed node GEMM output
__device__ float g_Wpack[DD * ZCOLS];
__device__ float g_bpack[ZCOLS];
__device__ float g_agg[NN * DD];               // SAGE sum -> mean (in place)
__device__ float g_cnt[NN];
__device__ float g_mw[NN * DD];                // mean @ sage_Wl
__device__ float g_mt[NN * HH];                // transformer seg-max
__device__ float g_st[NN * HH];                // transformer seg-sum
__device__ float g_elog[EE * HH];              // transformer logits -> exp values
__device__ float g_outt[NN * DD];              // transformer aggregation
__device__ float g_as[NN * HH];
__device__ float g_ad[NN * HH];
__device__ float g_gm[NN * HH];                // GAT seg-max
__device__ float g_gsum[NN * HH];              // GAT seg-sum
__device__ float g_glog[EE * HH];              // GAT edge logits -> exp
__device__ float g_lself[NN * HH];             // GAT self-loop logits -> exp
__device__ float g_outg[NN * DD];              // GAT aggregation
__device__ float g_cat[NN * 3 * DD];
__device__ float g_y[NN * DD];                 // cat @ fus_W + fus_b

// ---------------- helpers ------------------------------------------------------
__device__ __forceinline__ void atomicMaxFloat(float* addr, float val) {
    int* a = (int*)addr;
    int old = __float_as_int(*addr);
    while (__int_as_float(old) < val) {
        int prev = atomicCAS(a, old, __float_as_int(val));
        if (prev == old) break;
        old = prev;
    }
}

__device__ __forceinline__ unsigned f2tf(float f) {
    unsigned r;
    asm("cvt.rna.tf32.f32 %0, %1;" : "=r"(r) : "f"(f));
    return r;
}

// ---------------- init ---------------------------------------------------------
__global__ void k_init() {
    int i = blockIdx.x * blockDim.x + threadIdx.x;
    if (i < NN * DD) {
        g_agg[i] = 0.f; g_outt[i] = 0.f; g_outg[i] = 0.f;
    }
    if (i < NN) g_cnt[i] = 0.f;
    if (i < NN * HH) {
        g_mt[i] = -FLT_MAX; g_st[i] = 0.f;
        g_gm[i] = -FLT_MAX; g_gsum[i] = 0.f;
    }
}

// ---------------- pack weights [sage_Wr | tskip | Q | K | V | G] ---------------
__global__ void k_pack(const float* __restrict__ Wr, const float* __restrict__ Wsk,
                       const float* __restrict__ Wq, const float* __restrict__ Wk,
                       const float* __restrict__ Wv, const float* __restrict__ Wg,
                       const float* __restrict__ sb, const float* __restrict__ skb,
                       const float* __restrict__ qb, const float* __restrict__ kb,
                       const float* __restrict__ vb) {
    int i = blockIdx.x * blockDim.x + threadIdx.x;
    if (i >= DD * ZCOLS) return;
    int k = i / ZCOLS, c = i % ZCOLS;
    float w;
    if (c < 256) {
        w = (c < 128) ? Wr[k * 128 + c] : Wsk[k * 128 + (c - 128)];
    } else if (c < 768)      w = Wq[k * 512 + (c - ZOFF_Q)];
    else if (c < 1280)       w = Wk[k * 512 + (c - ZOFF_K)];
    else if (c < 1792)       w = Wv[k * 512 + (c - ZOFF_V)];
    else                     w = Wg[k * 512 + (c - ZOFF_G)];
    g_Wpack[i] = w;
    if (k == 0) {
        float b;
        if (c < 128)        b = sb[c];
        else if (c < 256)   b = skb[c - 128];
        else if (c < 768)   b = qb[c - ZOFF_Q];
        else if (c < 1280)  b = kb[c - ZOFF_K];
        else if (c < 1792)  b = vb[c - ZOFF_V];
        else                b = 0.f;
        g_bpack[c] = b;
    }
}

// ---------------- SAGE neighbor scatter ----------------------------------------
__global__ void k_sage_scatter(const float* __restrict__ x, const int* __restrict__ ei) {
    int e = blockIdx.x, t = threadIdx.x;
    int src = ei[e], dst = ei[EE + e];
    atomicAdd(&g_agg[dst * DD + t], x[src * DD + t]);
    if (t == 0) atomicAdd(&g_cnt[dst], 1.f);
}

__global__ void k_mean() {
    int i = blockIdx.x * blockDim.x + threadIdx.x;
    if (i >= NN * DD) return;
    float c = g_cnt[i / DD];
    g_agg[i] = g_agg[i] / fmaxf(c, 1.f);
}

// ---------------- TF32 tensor-core GEMM: C[M,N] = A[M,K]*B[K,N] (+bias) --------
// BM=BN=128, BK=16, 256 threads = 8 warps (4 along M x 2 along N).
// Each warp computes 32x64 via m16n8k8 mma tiles (2 x 8 tiles).
// A smem stride 20, B smem stride 136 -> conflict-free fragment loads.
#define BM 128
#define BN 128
#define BK 16
#define SA 20
#define SB 136

__global__ __launch_bounds__(256, 1) void gemm_tf32(
    const float* __restrict__ A, const float* __restrict__ B,
    const float* __restrict__ bias, float* __restrict__ C,
    int M, int N, int K)
{
    __shared__ unsigned As[2][BM * SA];
    __shared__ unsigned Bs[2][BK * SB];
    int tid = threadIdx.x;
    int lane = tid & 31, warp = tid >> 5;
    int wm = warp & 3, wn = warp >> 2;      // 4 x 2 warps
    int gid = lane >> 2, tig = lane & 3;
    int rowBase = blockIdx.y * BM, colBase = blockIdx.x * BN;

    float acc[2][8][4];
#pragma unroll
    for (int mt = 0; mt < 2; mt++)
#pragma unroll
        for (int nt = 0; nt < 8; nt++)
#pragma unroll
            for (int i = 0; i < 4; i++) acc[mt][nt][i] = 0.f;

    // gmem staging mapping
    int aRow = tid >> 1;               // 0..127
    int aCol = (tid & 1) * 8;          // 0 or 8
    int bRow = tid >> 4;               // 0..15
    int bCol = (tid & 15) * 8;         // 0..120

    float4 sa0, sa1, sb0, sb1;

    // prologue: load tile 0
    {
        int gr = rowBase + aRow;
        if (gr < M) {
            const float* ap = A + (size_t)gr * K + aCol;
            sa0 = *reinterpret_cast<const float4*>(ap);
            sa1 = *reinterpret_cast<const float4*>(ap + 4);
        } else { sa0 = make_float4(0,0,0,0); sa1 = sa0; }
        const float* bp = B + (size_t)bRow * N + colBase + bCol;
        sb0 = *reinterpret_cast<const float4*>(bp);
        sb1 = *reinterpret_cast<const float4*>(bp + 4);
        unsigned* as = &As[0][aRow * SA + aCol];
        as[0]=f2tf(sa0.x); as[1]=f2tf(sa0.y); as[2]=f2tf(sa0.z); as[3]=f2tf(sa0.w);
        as[4]=f2tf(sa1.x); as[5]=f2tf(sa1.y); as[6]=f2tf(sa1.z); as[7]=f2tf(sa1.w);
        unsigned* bs = &Bs[0][bRow * SB + bCol];
        bs[0]=f2tf(sb0.x); bs[1]=f2tf(sb0.y); bs[2]=f2tf(sb0.z); bs[3]=f2tf(sb0.w);
        bs[4]=f2tf(sb1.x); bs[5]=f2tf(sb1.y); bs[6]=f2tf(sb1.z); bs[7]=f2tf(sb1.w);
    }
    __syncthreads();

    int ktiles = K / BK;
    int cur = 0;
    for (int kt = 0; kt < ktiles; kt++) {
        bool hasNext = (kt + 1 < ktiles);
        if (hasNext) {
            int k0 = (kt + 1) * BK;
            int gr = rowBase + aRow;
            if (gr < M) {
                const float* ap = A + (size_t)gr * K + k0 + aCol;
                sa0 = *reinterpret_cast<const float4*>(ap);
                sa1 = *reinterpret_cast<const float4*>(ap + 4);
            } else { sa0 = make_float4(0,0,0,0); sa1 = sa0; }
            const float* bp = B + (size_t)(k0 + bRow) * N + colBase + bCol;
            sb0 = *reinterpret_cast<const float4*>(bp);
            sb1 = *reinterpret_cast<const float4*>(bp + 4);
        }
        // compute on buffer cur
#pragma unroll
        for (int kk = 0; kk < BK; kk += 8) {
            unsigned af[2][4];
#pragma unroll
            for (int mt = 0; mt < 2; mt++) {
                int base = (wm * 32 + mt * 16 + gid) * SA + kk + tig;
                af[mt][0] = As[cur][base];
                af[mt][1] = As[cur][base + 8 * SA];
                af[mt][2] = As[cur][base + 4];
                af[mt][3] = As[cur][base + 8 * SA + 4];
            }
            unsigned bf[8][2];
#pragma unroll
            for (int nt = 0; nt < 8; nt++) {
                int col = wn * 64 + nt * 8 + gid;
                bf[nt][0] = Bs[cur][(kk + tig) * SB + col];
                bf[nt][1] = Bs[cur][(kk + tig + 4) * SB + col];
            }
#pragma unroll
            for (int mt = 0; mt < 2; mt++)
#pragma unroll
                for (int nt = 0; nt < 8; nt++) {
                    asm volatile(
                        "mma.sync.aligned.m16n8k8.row.col.f32.tf32.tf32.f32 "
                        "{%0,%1,%2,%3}, {%4,%5,%6,%7}, {%8,%9}, {%0,%1,%2,%3};"
                        : "+f"(acc[mt][nt][0]), "+f"(acc[mt][nt][1]),
                          "+f"(acc[mt][nt][2]), "+f"(acc[mt][nt][3])
                        : "r"(af[mt][0]), "r"(af[mt][1]), "r"(af[mt][2]), "r"(af[mt][3]),
                          "r"(bf[nt][0]), "r"(bf[nt][1]));
                }
        }
        if (hasNext) {
            int nxt = cur ^ 1;
            unsigned* as = &As[nxt][aRow * SA + aCol];
            as[0]=f2tf(sa0.x); as[1]=f2tf(sa0.y); as[2]=f2tf(sa0.z); as[3]=f2tf(sa0.w);
            as[4]=f2tf(sa1.x); as[5]=f2tf(sa1.y); as[6]=f2tf(sa1.z); as[7]=f2tf(sa1.w);
            unsigned* bs = &Bs[nxt][bRow * SB + bCol];
            bs[0]=f2tf(sb0.x); bs[1]=f2tf(sb0.y); bs[2]=f2tf(sb0.z); bs[3]=f2tf(sb0.w);
            bs[4]=f2tf(sb1.x); bs[5]=f2tf(sb1.y); bs[6]=f2tf(sb1.z); bs[7]=f2tf(sb1.w);
        }
        __syncthreads();
        cur ^= 1;
    }

    // epilogue
#pragma unroll
    for (int mt = 0; mt < 2; mt++) {
#pragma unroll
        for (int nt = 0; nt < 8; nt++) {
            int c = colBase + wn * 64 + nt * 8 + tig * 2;
            float b0 = bias ? bias[c] : 0.f;
            float b1 = bias ? bias[c + 1] : 0.f;
            int r0 = rowBase + wm * 32 + mt * 16 + gid;
            if (r0 < M) {
                float2 o = make_float2(acc[mt][nt][0] + b0, acc[mt][nt][1] + b1);
                *reinterpret_cast<float2*>(&C[(size_t)r0 * N + c]) = o;
            }
            int r1 = r0 + 8;
            if (r1 < M) {
                float2 o = make_float2(acc[mt][nt][2] + b0, acc[mt][nt][3] + b1);
                *reinterpret_cast<float2*>(&C[(size_t)r1 * N + c]) = o;
            }
        }
    }
}

// ---------------- GAT attention coefficients a_s, a_d --------------------------
__global__ void k_asad(const float* __restrict__ attS, const float* __restrict__ attD) {
    int w = (blockIdx.x * blockDim.x + threadIdx.x) >> 5;
    int lane = threadIdx.x & 31;
    if (w >= NN * HH) return;
    int n = w / HH, h = w % HH;
    const float* g = g_Z + (size_t)n * ZCOLS + ZOFF_G + h * DD;
    float s = 0.f, d = 0.f;
    for (int i = lane; i < DD; i += 32) {
        float gv = g[i];
        s += gv * attS[h * DD + i];
        d += gv * attD[h * DD + i];
    }
#pragma unroll
    for (int o = 16; o; o >>= 1) {
        s += __shfl_xor_sync(0xffffffffu, s, o);
        d += __shfl_xor_sync(0xffffffffu, d, o);
    }
    if (lane == 0) { g_as[n * HH + h] = s; g_ad[n * HH + h] = d; }
}

// ---------------- transformer edge logits + seg-max ----------------------------
__global__ void k_tlogit(const int* __restrict__ ei, const float* __restrict__ ea,
                         const float* __restrict__ teW) {
    int e = blockIdx.x, t = threadIdx.x;
    int src = ei[e], dst = ei[EE + e];
    __shared__ float sea[EDIM];
    __shared__ float red[HH][4];
    if (t < EDIM) sea[t] = ea[e * EDIM + t];
    __syncthreads();
    float acc[HH];
#pragma unroll
    for (int h = 0; h < HH; h++) {
        float ev = 0.f;
#pragma unroll
        for (int j = 0; j < EDIM; j++) ev += sea[j] * teW[j * 512 + h * DD + t];
        float qv = g_Z[(size_t)dst * ZCOLS + ZOFF_Q + h * DD + t];
        float kv = g_Z[(size_t)src * ZCOLS + ZOFF_K + h * DD + t];
        acc[h] = qv * (kv + ev);
    }
    int lane = t & 31, wp = t >> 5;
#pragma unroll
    for (int h = 0; h < HH; h++) {
        float v = acc[h];
#pragma unroll
        for (int o = 16; o; o >>= 1) v += __shfl_xor_sync(0xffffffffu, v, o);
        if (lane == 0) red[h][wp] = v;
    }
    __syncthreads();
    if (t < HH) {
        float v = (red[t][0] + red[t][1] + red[t][2] + red[t][3]) * 0.0883883476483184405f;
        g_elog[e * HH + t] = v;
        atomicMaxFloat(&g_mt[dst * HH + t], v);
    }
}

__global__ void k_texp(const int* __restrict__ ei) {
    int i = blockIdx.x * blockDim.x + threadIdx.x;
    if (i >= EE * HH) return;
    int e = i / HH, h = i % HH;
    int dst = ei[EE + e];
    float v = expf(g_elog[i] - g_mt[dst * HH + h]);
    g_elog[i] = v;
    atomicAdd(&g_st[dst * HH + h], v);
}

__global__ void k_taggr(const int* __restrict__ ei, const float* __restrict__ ea,
                        const float* __restrict__ teW) {
    int e = blockIdx.x, t = threadIdx.x;
    int src = ei[e], dst = ei[EE + e];
    __shared__ float sea[EDIM];
    __shared__ float w[HH];
    if (t < EDIM) sea[t] = ea[e * EDIM + t];
    if (t < HH) w[t] = g_elog[e * HH + t] / (g_st[dst * HH + t] + 1e-16f) * 0.25f;
    __syncthreads();
    float acc = 0.f;
#pragma unroll
    for (int h = 0; h < HH; h++) {
        float ev = 0.f;
#pragma unroll
        for (int j = 0; j < EDIM; j++) ev += sea[j] * teW[j * 512 + h * DD + t];
        float vv = g_Z[(size_t)src * ZCOLS + ZOFF_V + h * DD + t];
        acc += w[h] * (vv + ev);
    }
    atomicAdd(&g_outt[dst * DD + t], acc);
}

// ---------------- GAT logits / softmax / aggregation (edges + self loops) ------
__global__ void k_glogit(const int* __restrict__ ei) {
    int i = blockIdx.x * blockDim.x + threadIdx.x;
    if (i < EE * HH) {
        int e = i / HH, h = i % HH;
        int s = ei[e], d = ei[EE + e];
        float v = g_as[s * HH + h] + g_ad[d * HH + h];
        v = (v > 0.f) ? v : 0.2f * v;
        g_glog[i] = v;
        atomicMaxFloat(&g_gm[d * HH + h], v);
    } else if (i < (EE + NN) * HH) {
        int j = i - EE * HH;
        int n = j / HH, h = j % HH;
        float v = g_as[n * HH + h] + g_ad[n * HH + h];
        v = (v > 0.f) ? v : 0.2f * v;
        g_lself[j] = v;
        atomicMaxFloat(&g_gm[n * HH + h], v);
    }
}

__global__ void k_gexp(const int* __restrict__ ei) {
    int i = blockIdx.x * blockDim.x + threadIdx.x;
    if (i < EE * HH) {
        int e = i / HH, h = i % HH;
        int d = ei[EE + e];
        float v = expf(g_glog[i] - g_gm[d * HH + h]);
        g_glog[i] = v;
        atomicAdd(&g_gsum[d * HH + h], v);
    } else if (i < (EE + NN) * HH) {
        int j = i - EE * HH;
        int n = j / HH, h = j % HH;
        float v = expf(g_lself[j] - g_gm[n * HH + h]);
        g_lself[j] = v;
        atomicAdd(&g_gsum[n * HH + h], v);
    }
}

__global__ void k_gaggr(const int* __restrict__ ei) {
    int b = blockIdx.x, t = threadIdx.x;
    int src, dst;
    const float* lw;
    if (b < EE) { src = ei[b]; dst = ei[EE + b]; lw = &g_glog[b * HH]; }
    else        { src = b - EE; dst = src;       lw = &g_lself[src * HH]; }
    __shared__ float w[HH];
    if (t < HH) w[t] = lw[t] / (g_gsum[dst * HH + t] + 1e-16f) * 0.25f;
    __syncthreads();
    float acc = 0.f;
#pragma unroll
    for (int h = 0; h < HH; h++)
        acc += w[h] * g_Z[(size_t)src * ZCOLS + ZOFF_G + h * DD + t];
    atomicAdd(&g_outg[dst * DD + t], acc);
}

// ---------------- combine branches into cat ------------------------------------
__global__ void k_combine(const float* __restrict__ gatb,
                          const float* __restrict__ gsh, const float* __restrict__ gatt,
                          const float* __restrict__ gnb) {
    int i = blockIdx.x * blockDim.x + threadIdx.x;
    if (i >= NN * DD) return;
    int n = i / DD, d = i % DD;
    float s_s = 1.f / (1.f + expf(-gsh[0]));
    float s_a = 1.f / (1.f + expf(-gatt[0]));
    float s_n = 1.f / (1.f + expf(-gnb[0]));
    float xs = g_mw[i] + g_Z[(size_t)n * ZCOLS + ZOFF_R + d];       // sage_b already in bpack
    xs = fmaxf(xs, 0.f);
    float xa = g_outt[i] + g_Z[(size_t)n * ZCOLS + ZOFF_SKIP + d];  // tskip_b in bpack
    xa = fmaxf(xa, 0.f);
    float xn = fmaxf(g_outg[i] + gatb[d], 0.f);
    g_cat[(size_t)n * 384 + d]       = xs * s_s;
    g_cat[(size_t)n * 384 + 128 + d] = xa * s_a;
    g_cat[(size_t)n * 384 + 256 + d] = xn * s_n;
}

// ---------------- final: LN -> relu -> residual -> LN ---------------------------
__global__ void k_final(const float* __restrict__ x,
                        const float* __restrict__ fg, const float* __restrict__ fb,
                        const float* __restrict__ ng, const float* __restrict__ nb,
                        float* __restrict__ out) {
    int n = blockIdx.x, t = threadIdx.x;
    __shared__ float sh[4];
    float v = g_y[n * DD + t];
    float s = v;
#pragma unroll
    for (int o = 16; o; o >>= 1) s += __shfl_xor_sync(0xffffffffu, s, o);
    if ((t & 31) == 0) sh[t >> 5] = s;
    __syncthreads();
    float mean = (sh[0] + sh[1] + sh[2] + sh[3]) * (1.f / DD);
    __syncthreads();
    float dv = v - mean;
    float s2 = dv * dv;
#pragma unroll
    for (int o = 16; o; o >>= 1) s2 += __shfl_xor_sync(0xffffffffu, s2, o);
    if ((t & 31) == 0) sh[t >> 5] = s2;
    __syncthreads();
    float var = (sh[0] + sh[1] + sh[2] + sh[3]) * (1.f / DD);
    float ln1 = dv * rsqrtf(var + 1e-5f) * fg[t] + fb[t];
    float r = x[n * DD + t] + fmaxf(ln1, 0.f);
    __syncthreads();
    s = r;
#pragma unroll
    for (int o = 16; o; o >>= 1) s += __shfl_xor_sync(0xffffffffu, s, o);
    if ((t & 31) == 0) sh[t >> 5] = s;
    __syncthreads();
    float mean2 = (sh[0] + sh[1] + sh[2] + sh[3]) * (1.f / DD);
    __syncthreads();
    float dr = r - mean2;
    s2 = dr * dr;
#pragma unroll
    for (int o = 16; o; o >>= 1) s2 += __shfl_xor_sync(0xffffffffu, s2, o);
    if ((t & 31) == 0) sh[t >> 5] = s2;
    __syncthreads();
    float var2 = (sh[0] + sh[1] + sh[2] + sh[3]) * (1.f / DD);
    out[n * DD + t] = dr * rsqrtf(var2 + 1e-5f) * ng[t] + nb[t];
}

// ---------------- launch --------------------------------------------------------
extern "C" void kernel_launch(void* const* d_in, const int* in_sizes, int n_in,
                              void* d_out, int out_size) {
    const float* x       = (const float*)d_in[0];
    const int*   ei      = (const int*)d_in[1];
    const float* ea      = (const float*)d_in[2];
    const float* sage_Wl = (const float*)d_in[3];
    const float* sage_Wr = (const float*)d_in[4];
    const float* sage_b  = (const float*)d_in[5];
    const float* tqW = (const float*)d_in[6];
    const float* tqb = (const float*)d_in[7];
    const float* tkW = (const float*)d_in[8];
    const float* tkb = (const float*)d_in[9];
    const float* tvW = (const float*)d_in[10];
    const float* tvb = (const float*)d_in[11];
    const float* teW = (const float*)d_in[12];
    const float* tskW = (const float*)d_in[13];
    const float* tskb = (const float*)d_in[14];
    const float* gatW = (const float*)d_in[15];
    const float* attS = (const float*)d_in[16];
    const float* attD = (const float*)d_in[17];
    const float* gatb = (const float*)d_in[18];
    const float* gsh  = (const float*)d_in[19];
    const float* gatt = (const float*)d_in[20];
    const float* gnb  = (const float*)d_in[21];
    const float* fusW = (const float*)d_in[22];
    const float* fusb = (const float*)d_in[23];
    const float* fusg = (const float*)d_in[24];
    const float* fusbe = (const float*)d_in[25];
    const float* ng   = (const float*)d_in[26];
    const float* nb   = (const float*)d_in[27];
    float* out = (float*)d_out;

    float *pZ, *pWp, *pbp, *pagg, *pmw, *pcat, *py;
    cudaGetSymbolAddress((void**)&pZ, g_Z);
    cudaGetSymbolAddress((void**)&pWp, g_Wpack);
    cudaGetSymbolAddress((void**)&pbp, g_bpack);
    cudaGetSymbolAddress((void**)&pagg, g_agg);
    cudaGetSymbolAddress((void**)&pmw, g_mw);
    cudaGetSymbolAddress((void**)&pcat, g_cat);
    cudaGetSymbolAddress((void**)&py, g_y);

    k_init<<<(NN * DD + 255) / 256, 256>>>();
    k_pack<<<(DD * ZCOLS + 255) / 256, 256>>>(sage_Wr, tskW, tqW, tkW, tvW, gatW,
                                              sage_b, tskb, tqb, tkb, tvb);
    k_sage_scatter<<<EE, DD>>>(x, ei);

    dim3 gZ(ZCOLS / 128, (NN + 127) / 128);
    gemm_tf32<<<gZ, 256>>>(x, pWp, pbp, pZ, NN, ZCOLS, DD);

    k_mean<<<(NN * DD + 255) / 256, 256>>>();
    gemm_tf32<<<dim3(1, (NN + 127) / 128), 256>>>(pagg, sage_Wl, nullptr, pmw, NN, DD, DD);

    k_asad<<<(NN * HH * 32 + 255) / 256, 256>>>(attS, attD);

    k_tlogit<<<EE, DD>>>(ei, ea, teW);
    k_texp<<<(EE * HH + 255) / 256, 256>>>(ei);
    k_taggr<<<EE, DD>>>(ei, ea, teW);

    k_glogit<<<((EE + NN) * HH + 255) / 256, 256>>>(ei);
    k_gexp<<<((EE + NN) * HH + 255) / 256, 256>>>(ei);
    k_gaggr<<<EE + NN, DD>>>(ei);

    k_combine<<<(NN * DD + 255) / 256, 256>>>(gatb, gsh, gatt, gnb);
    gemm_tf32<<<dim3(1, (NN + 127) / 128), 256>>>(pcat, fusW, fusb, py, NN, DD, 3 * DD);
    k_final<<<NN, DD>>>(x, fusg, fusbe, ng, nb, out);
}

// round 4
// speedup vs baseline: 1.4034x; 1.0383x over previous
#include <cuda_runtime.h>
#include <math.h>
#include <float.h>

#define NN 50000
#define EE 150000
#define DD 128
#define HH 4
#define EDIM 16
#define ZCOLS 2304
// Z column layout: [xWr | xWskip+b | Q | K | V | G]
#define ZOFF_R 0
#define ZOFF_SKIP 128
#define ZOFF_Q 256
#define ZOFF_K 768
#define ZOFF_V 1280
#define ZOFF_G 1792

// ---------------- scratch (static device allocations; no cudaMalloc) ----------
__device__ float g_Z[(size_t)NN * ZCOLS];
__device__ float g_Wpack[DD * ZCOLS];
__device__ float g_bpack[ZCOLS];
__device__ float g_agg[NN * DD];
__device__ float g_cnt[NN];
__device__ float g_mw[NN * DD];
__device__ float g_st[NN * HH];                // transformer seg-sum of exp
__device__ float g_elog[EE * HH];              // transformer exp(logit)
__device__ float g_outt[NN * DD];
__device__ float g_as[NN * HH];
__device__ float g_ad[NN * HH];
__device__ float g_gsum[NN * HH];              // GAT seg-sum of exp
__device__ float g_glog[EE * HH];              // GAT exp(logit), edges
__device__ float g_lself[NN * HH];             // GAT exp(logit), self loops
__device__ float g_outg[NN * DD];
__device__ float g_cat[NN * 3 * DD];
__device__ float g_y[NN * DD];

// ---------------- helpers ------------------------------------------------------
__device__ __forceinline__ unsigned f2tf(float f) {
    unsigned r;
    asm("cvt.rna.tf32.f32 %0, %1;" : "=r"(r) : "f"(f));
    return r;
}

#define CP_ASYNC16(dst_u32, src_ptr) \
    asm volatile("cp.async.cg.shared.global [%0], [%1], 16;" :: "r"(dst_u32), "l"(src_ptr))
#define CP_COMMIT() asm volatile("cp.async.commit_group;")
#define CP_WAIT(N)  asm volatile("cp.async.wait_group %0;" :: "n"(N))

// ---------------- init ---------------------------------------------------------
__global__ void k_init() {
    int i = blockIdx.x * blockDim.x + threadIdx.x;
    if (i < NN * DD) {
        g_agg[i] = 0.f; g_outt[i] = 0.f; g_outg[i] = 0.f;
    }
    if (i < NN) g_cnt[i] = 0.f;
    if (i < NN * HH) { g_st[i] = 0.f; g_gsum[i] = 0.f; }
}

// ---------------- pack weights [sage_Wr | tskip | Q | K | V | G] ---------------
__global__ void k_pack(const float* __restrict__ Wr, const float* __restrict__ Wsk,
                       const float* __restrict__ Wq, const float* __restrict__ Wk,
                       const float* __restrict__ Wv, const float* __restrict__ Wg,
                       const float* __restrict__ sb, const float* __restrict__ skb,
                       const float* __restrict__ qb, const float* __restrict__ kb,
                       const float* __restrict__ vb) {
    int i = blockIdx.x * blockDim.x + threadIdx.x;
    if (i >= DD * ZCOLS) return;
    int k = i / ZCOLS, c = i % ZCOLS;
    float w;
    if (c < 256) {
        w = (c < 128) ? Wr[k * 128 + c] : Wsk[k * 128 + (c - 128)];
    } else if (c < 768)      w = Wq[k * 512 + (c - ZOFF_Q)];
    else if (c < 1280)       w = Wk[k * 512 + (c - ZOFF_K)];
    else if (c < 1792)       w = Wv[k * 512 + (c - ZOFF_V)];
    else                     w = Wg[k * 512 + (c - ZOFF_G)];
    g_Wpack[i] = w;
    if (k == 0) {
        float b;
        if (c < 128)        b = sb[c];
        else if (c < 256)   b = skb[c - 128];
        else if (c < 768)   b = qb[c - ZOFF_Q];
        else if (c < 1280)  b = kb[c - ZOFF_K];
        else if (c < 1792)  b = vb[c - ZOFF_V];
        else                b = 0.f;
        g_bpack[c] = b;
    }
}

// ---------------- SAGE neighbor scatter ----------------------------------------
__global__ void k_sage_scatter(const float* __restrict__ x, const int* __restrict__ ei) {
    int e = blockIdx.x, t = threadIdx.x;
    int src = ei[e], dst = ei[EE + e];
    atomicAdd(&g_agg[dst * DD + t], x[src * DD + t]);
    if (t == 0) atomicAdd(&g_cnt[dst], 1.f);
}

__global__ void k_mean() {
    int i = blockIdx.x * blockDim.x + threadIdx.x;
    if (i >= NN * DD) return;
    float c = g_cnt[i / DD];
    g_agg[i] = g_agg[i] / fmaxf(c, 1.f);
}

// ---------------- TF32 tensor-core GEMM (cp.async pipelined) -------------------
// BM=BN=128, BK=16, 512 threads = 16 warps (4x4), each warp 32x32.
#define BM 128
#define BN 128
#define BK 16
#define SA 20
#define SB 136

__global__ __launch_bounds__(512, 1) void gemm_tf32(
    const float* __restrict__ A, const float* __restrict__ B,
    const float* __restrict__ bias, float* __restrict__ C,
    int M, int N, int K)
{
    __shared__ float As[2][BM * SA];
    __shared__ float Bs[2][BK * SB];
    int tid = threadIdx.x;
    int lane = tid & 31, warp = tid >> 5;
    int wm = warp & 3, wn = warp >> 2;          // 4 x 4 warps
    int gid = lane >> 2, tig = lane & 3;
    int rowBase = blockIdx.y * BM, colBase = blockIdx.x * BN;

    float acc[2][4][4];
#pragma unroll
    for (int mt = 0; mt < 2; mt++)
#pragma unroll
        for (int nt = 0; nt < 4; nt++)
#pragma unroll
            for (int i = 0; i < 4; i++) acc[mt][nt][i] = 0.f;

    // staging maps (512 threads)
    int aRow = tid >> 2, aCol = (tid & 3) * 4;    // 128 x 16
    int bRow = tid >> 5, bCol = (tid & 31) * 4;   // 16 x 128
    int aGr = rowBase + aRow; if (aGr > M - 1) aGr = M - 1;   // clamp (rows >= M never stored)
    const float* aSrcBase = A + (size_t)aGr * K + aCol;
    const float* bSrcBase = B + (size_t)bRow * N + colBase + bCol;

    unsigned aDst[2], bDst[2];
#pragma unroll
    for (int s = 0; s < 2; s++) {
        aDst[s] = (unsigned)__cvta_generic_to_shared(&As[s][aRow * SA + aCol]);
        bDst[s] = (unsigned)__cvta_generic_to_shared(&Bs[s][bRow * SB + bCol]);
    }

    // prologue: stage 0
    CP_ASYNC16(aDst[0], aSrcBase);
    CP_ASYNC16(bDst[0], bSrcBase);
    CP_COMMIT();

    int ktiles = K / BK;
    int cur = 0;
    for (int kt = 0; kt < ktiles; kt++) {
        if (kt + 1 < ktiles) {
            int k0 = (kt + 1) * BK;
            CP_ASYNC16(aDst[cur ^ 1], aSrcBase + k0);
            CP_ASYNC16(bDst[cur ^ 1], bSrcBase + (size_t)k0 * N);
            CP_COMMIT();
            CP_WAIT(1);
        } else {
            CP_WAIT(0);
        }
        __syncthreads();

#pragma unroll
        for (int kk = 0; kk < BK; kk += 8) {
            unsigned af[2][4];
#pragma unroll
            for (int mt = 0; mt < 2; mt++) {
                int base = (wm * 32 + mt * 16 + gid) * SA + kk + tig;
                af[mt][0] = f2tf(As[cur][base]);
                af[mt][1] = f2tf(As[cur][base + 8 * SA]);
                af[mt][2] = f2tf(As[cur][base + 4]);
                af[mt][3] = f2tf(As[cur][base + 8 * SA + 4]);
            }
            unsigned bf[4][2];
#pragma unroll
            for (int nt = 0; nt < 4; nt++) {
                int col = wn * 32 + nt * 8 + gid;
                bf[nt][0] = f2tf(Bs[cur][(kk + tig) * SB + col]);
                bf[nt][1] = f2tf(Bs[cur][(kk + tig + 4) * SB + col]);
            }
#pragma unroll
            for (int mt = 0; mt < 2; mt++)
#pragma unroll
                for (int nt = 0; nt < 4; nt++) {
                    asm volatile(
                        "mma.sync.aligned.m16n8k8.row.col.f32.tf32.tf32.f32 "
                        "{%0,%1,%2,%3}, {%4,%5,%6,%7}, {%8,%9}, {%0,%1,%2,%3};"
                        : "+f"(acc[mt][nt][0]), "+f"(acc[mt][nt][1]),
                          "+f"(acc[mt][nt][2]), "+f"(acc[mt][nt][3])
                        : "r"(af[mt][0]), "r"(af[mt][1]), "r"(af[mt][2]), "r"(af[mt][3]),
                          "r"(bf[nt][0]), "r"(bf[nt][1]));
                }
        }
        __syncthreads();
        cur ^= 1;
    }

    // epilogue
#pragma unroll
    for (int mt = 0; mt < 2; mt++) {
#pragma unroll
        for (int nt = 0; nt < 4; nt++) {
            int c = colBase + wn * 32 + nt * 8 + tig * 2;
            float b0 = bias ? bias[c] : 0.f;
            float b1 = bias ? bias[c + 1] : 0.f;
            int r0 = rowBase + wm * 32 + mt * 16 + gid;
            if (r0 < M) {
                float2 o = make_float2(acc[mt][nt][0] + b0, acc[mt][nt][1] + b1);
                *reinterpret_cast<float2*>(&C[(size_t)r0 * N + c]) = o;
            }
            int r1 = r0 + 8;
            if (r1 < M) {
                float2 o = make_float2(acc[mt][nt][2] + b0, acc[mt][nt][3] + b1);
                *reinterpret_cast<float2*>(&C[(size_t)r1 * N + c]) = o;
            }
        }
    }
}

// ---------------- GAT attention coefficients a_s, a_d --------------------------
__global__ void k_asad(const float* __restrict__ attS, const float* __restrict__ attD) {
    int w = (blockIdx.x * blockDim.x + threadIdx.x) >> 5;
    int lane = threadIdx.x & 31;
    if (w >= NN * HH) return;
    int n = w / HH, h = w % HH;
    const float* g = g_Z + (size_t)n * ZCOLS + ZOFF_G + h * DD;
    float s = 0.f, d = 0.f;
    for (int i = lane; i < DD; i += 32) {
        float gv = g[i];
        s += gv * attS[h * DD + i];
        d += gv * attD[h * DD + i];
    }
#pragma unroll
    for (int o = 16; o; o >>= 1) {
        s += __shfl_xor_sync(0xffffffffu, s, o);
        d += __shfl_xor_sync(0xffffffffu, d, o);
    }
    if (lane == 0) { g_as[n * HH + h] = s; g_ad[n * HH + h] = d; }
}

// ---------------- transformer logits: exp + segment-sum (no max; shift-safe) ---
__global__ void k_tlogit(const int* __restrict__ ei, const float* __restrict__ ea,
                         const float* __restrict__ teW) {
    int e = blockIdx.x, t = threadIdx.x;
    int src = ei[e], dst = ei[EE + e];
    __shared__ float sea[EDIM];
    __shared__ float red[HH][4];
    if (t < EDIM) sea[t] = ea[e * EDIM + t];
    __syncthreads();
    float acc[HH];
#pragma unroll
    for (int h = 0; h < HH; h++) {
        float ev = 0.f;
#pragma unroll
        for (int j = 0; j < EDIM; j++) ev += sea[j] * teW[j * 512 + h * DD + t];
        float qv = g_Z[(size_t)dst * ZCOLS + ZOFF_Q + h * DD + t];
        float kv = g_Z[(size_t)src * ZCOLS + ZOFF_K + h * DD + t];
        acc[h] = qv * (kv + ev);
    }
    int lane = t & 31, wp = t >> 5;
#pragma unroll
    for (int h = 0; h < HH; h++) {
        float v = acc[h];
#pragma unroll
        for (int o = 16; o; o >>= 1) v += __shfl_xor_sync(0xffffffffu, v, o);
        if (lane == 0) red[h][wp] = v;
    }
    __syncthreads();
    if (t < HH) {
        float v = (red[t][0] + red[t][1] + red[t][2] + red[t][3]) * 0.0883883476483184405f;
        float ex = expf(v);
        g_elog[e * HH + t] = ex;
        atomicAdd(&g_st[dst * HH + t], ex);
    }
}

__global__ void k_taggr(const int* __restrict__ ei, const float* __restrict__ ea,
                        const float* __restrict__ teW) {
    int e = blockIdx.x, t = threadIdx.x;
    int src = ei[e], dst = ei[EE + e];
    __shared__ float sea[EDIM];
    __shared__ float w[HH];
    if (t < EDIM) sea[t] = ea[e * EDIM + t];
    if (t < HH) w[t] = g_elog[e * HH + t] / (g_st[dst * HH + t] + 1e-16f) * 0.25f;
    __syncthreads();
    float acc = 0.f;
#pragma unroll
    for (int h = 0; h < HH; h++) {
        float ev = 0.f;
#pragma unroll
        for (int j = 0; j < EDIM; j++) ev += sea[j] * teW[j * 512 + h * DD + t];
        float vv = g_Z[(size_t)src * ZCOLS + ZOFF_V + h * DD + t];
        acc += w[h] * (vv + ev);
    }
    atomicAdd(&g_outt[dst * DD + t], acc);
}

// ---------------- GAT logits: leaky -> exp -> segment-sum (no max) -------------
__global__ void k_glogit(const int* __restrict__ ei) {
    int i = blockIdx.x * blockDim.x + threadIdx.x;
    if (i < EE * HH) {
        int e = i / HH, h = i % HH;
        int s = ei[e], d = ei[EE + e];
        float v = g_as[s * HH + h] + g_ad[d * HH + h];
        v = (v > 0.f) ? v : 0.2f * v;
        float ex = expf(v);
        g_glog[i] = ex;
        atomicAdd(&g_gsum[d * HH + h], ex);
    } else if (i < (EE + NN) * HH) {
        int j = i - EE * HH;
        int n = j / HH, h = j % HH;
        float v = g_as[n * HH + h] + g_ad[n * HH + h];
        v = (v > 0.f) ? v : 0.2f * v;
        float ex = expf(v);
        g_lself[j] = ex;
        atomicAdd(&g_gsum[n * HH + h], ex);
    }
}

__global__ void k_gaggr(const int* __restrict__ ei) {
    int b = blockIdx.x, t = threadIdx.x;
    int src, dst;
    const float* lw;
    if (b < EE) { src = ei[b]; dst = ei[EE + b]; lw = &g_glog[b * HH]; }
    else        { src = b - EE; dst = src;       lw = &g_lself[src * HH]; }
    __shared__ float w[HH];
    if (t < HH) w[t] = lw[t] / (g_gsum[dst * HH + t] + 1e-16f) * 0.25f;
    __syncthreads();
    float acc = 0.f;
#pragma unroll
    for (int h = 0; h < HH; h++)
        acc += w[h] * g_Z[(size_t)src * ZCOLS + ZOFF_G + h * DD + t];
    atomicAdd(&g_outg[dst * DD + t], acc);
}

// ---------------- combine branches into cat ------------------------------------
__global__ void k_combine(const float* __restrict__ gatb,
                          const float* __restrict__ gsh, const float* __restrict__ gatt,
                          const float* __restrict__ gnb) {
    int i = blockIdx.x * blockDim.x + threadIdx.x;
    if (i >= NN * DD) return;
    int n = i / DD, d = i % DD;
    float s_s = 1.f / (1.f + expf(-gsh[0]));
    float s_a = 1.f / (1.f + expf(-gatt[0]));
    float s_n = 1.f / (1.f + expf(-gnb[0]));
    float xs = g_mw[i] + g_Z[(size_t)n * ZCOLS + ZOFF_R + d];
    xs = fmaxf(xs, 0.f);
    float xa = g_outt[i] + g_Z[(size_t)n * ZCOLS + ZOFF_SKIP + d];
    xa = fmaxf(xa, 0.f);
    float xn = fmaxf(g_outg[i] + gatb[d], 0.f);
    g_cat[(size_t)n * 384 + d]       = xs * s_s;
    g_cat[(size_t)n * 384 + 128 + d] = xa * s_a;
    g_cat[(size_t)n * 384 + 256 + d] = xn * s_n;
}

// ---------------- final: LN -> relu -> residual -> LN ---------------------------
__global__ void k_final(const float* __restrict__ x,
                        const float* __restrict__ fg, const float* __restrict__ fb,
                        const float* __restrict__ ng, const float* __restrict__ nb,
                        float* __restrict__ out) {
    int n = blockIdx.x, t = threadIdx.x;
    __shared__ float sh[4];
    float v = g_y[n * DD + t];
    float s = v;
#pragma unroll
    for (int o = 16; o; o >>= 1) s += __shfl_xor_sync(0xffffffffu, s, o);
    if ((t & 31) == 0) sh[t >> 5] = s;
    __syncthreads();
    float mean = (sh[0] + sh[1] + sh[2] + sh[3]) * (1.f / DD);
    __syncthreads();
    float dv = v - mean;
    float s2 = dv * dv;
#pragma unroll
    for (int o = 16; o; o >>= 1) s2 += __shfl_xor_sync(0xffffffffu, s2, o);
    if ((t & 31) == 0) sh[t >> 5] = s2;
    __syncthreads();
    float var = (sh[0] + sh[1] + sh[2] + sh[3]) * (1.f / DD);
    float ln1 = dv * rsqrtf(var + 1e-5f) * fg[t] + fb[t];
    float r = x[n * DD + t] + fmaxf(ln1, 0.f);
    __syncthreads();
    s = r;
#pragma unroll
    for (int o = 16; o; o >>= 1) s += __shfl_xor_sync(0xffffffffu, s, o);
    if ((t & 31) == 0) sh[t >> 5] = s;
    __syncthreads();
    float mean2 = (sh[0] + sh[1] + sh[2] + sh[3]) * (1.f / DD);
    __syncthreads();
    float dr = r - mean2;
    s2 = dr * dr;
#pragma unroll
    for (int o = 16; o; o >>= 1) s2 += __shfl_xor_sync(0xffffffffu, s2, o);
    if ((t & 31) == 0) sh[t >> 5] = s2;
    __syncthreads();
    float var2 = (sh[0] + sh[1] + sh[2] + sh[3]) * (1.f / DD);
    out[n * DD + t] = dr * rsqrtf(var2 + 1e-5f) * ng[t] + nb[t];
}

// ---------------- launch --------------------------------------------------------
extern "C" void kernel_launch(void* const* d_in, const int* in_sizes, int n_in,
                              void* d_out, int out_size) {
    const float* x       = (const float*)d_in[0];
    const int*   ei      = (const int*)d_in[1];
    const float* ea      = (const float*)d_in[2];
    const float* sage_Wl = (const float*)d_in[3];
    const float* sage_Wr = (const float*)d_in[4];
    const float* sage_b  = (const float*)d_in[5];
    const float* tqW = (const float*)d_in[6];
    const float* tqb = (const float*)d_in[7];
    const float* tkW = (const float*)d_in[8];
    const float* tkb = (const float*)d_in[9];
    const float* tvW = (const float*)d_in[10];
    const float* tvb = (const float*)d_in[11];
    const float* teW = (const float*)d_in[12];
    const float* tskW = (const float*)d_in[13];
    const float* tskb = (const float*)d_in[14];
    const float* gatW = (const float*)d_in[15];
    const float* attS = (const float*)d_in[16];
    const float* attD = (const float*)d_in[17];
    const float* gatb = (const float*)d_in[18];
    const float* gsh  = (const float*)d_in[19];
    const float* gatt = (const float*)d_in[20];
    const float* gnb  = (const float*)d_in[21];
    const float* fusW = (const float*)d_in[22];
    const float* fusb = (const float*)d_in[23];
    const float* fusg = (const float*)d_in[24];
    const float* fusbe = (const float*)d_in[25];
    const float* ng   = (const float*)d_in[26];
    const float* nb   = (const float*)d_in[27];
    float* out = (float*)d_out;

    float *pZ, *pWp, *pbp, *pagg, *pmw, *pcat, *py;
    cudaGetSymbolAddress((void**)&pZ, g_Z);
    cudaGetSymbolAddress((void**)&pWp, g_Wpack);
    cudaGetSymbolAddress((void**)&pbp, g_bpack);
    cudaGetSymbolAddress((void**)&pagg, g_agg);
    cudaGetSymbolAddress((void**)&pmw, g_mw);
    cudaGetSymbolAddress((void**)&pcat, g_cat);
    cudaGetSymbolAddress((void**)&py, g_y);

    k_init<<<(NN * DD + 255) / 256, 256>>>();
    k_pack<<<(DD * ZCOLS + 255) / 256, 256>>>(sage_Wr, tskW, tqW, tkW, tvW, gatW,
                                              sage_b, tskb, tqb, tkb, tvb);
    k_sage_scatter<<<EE, DD>>>(x, ei);

    dim3 gZ(ZCOLS / 128, (NN + 127) / 128);
    gemm_tf32<<<gZ, 512>>>(x, pWp, pbp, pZ, NN, ZCOLS, DD);

    k_mean<<<(NN * DD + 255) / 256, 256>>>();
    gemm_tf32<<<dim3(1, (NN + 127) / 128), 512>>>(pagg, sage_Wl, nullptr, pmw, NN, DD, DD);

    k_asad<<<(NN * HH * 32 + 255) / 256, 256>>>(attS, attD);

    k_tlogit<<<EE, DD>>>(ei, ea, teW);
    k_taggr<<<EE, DD>>>(ei, ea, teW);

    k_glogit<<<((EE + NN) * HH + 255) / 256, 256>>>(ei);
    k_gaggr<<<EE + NN, DD>>>(ei);

    k_combine<<<(NN * DD + 255) / 256, 256>>>(gatb, gsh, gatt, gnb);
    gemm_tf32<<<dim3(1, (NN + 127) / 128), 512>>>(pcat, fusW, fusb, py, NN, DD, 3 * DD);
    k_final<<<NN, DD>>>(x, fusg, fusbe, ng, nb, out);
}